// round 1
// baseline (speedup 1.0000x reference)
#include <cuda_runtime.h>
#include <cuda_bf16.h>

// Problem constants
#define S_ 2048
#define DIM_ 2048
#define H_ 16
#define NOPE_ 128
#define ROPE_ 64
#define VD_ 128
#define LORA_ 512
#define QKH_ 192            // NOPE + ROPE
#define KVW_ 576            // LORA + ROPE
#define SCALE_ 0.07216878364870323f  // 192^-0.5

// ---------------------------------------------------------------------------
// Scratch (static __device__ arrays; allocation is forbidden)
// ---------------------------------------------------------------------------
__device__ float d_q     [(long)S_ * (H_ * QKH_)];     // 2048 x 3072
__device__ float d_kv    [(long)S_ * KVW_];            // 2048 x 576
__device__ float d_qeff  [(long)H_ * S_ * KVW_];       // 16 x 2048 x 576 (q_c | q_pe)
__device__ float d_keff  [(long)S_ * KVW_];            // 2048 x 576 (kv_c_norm | k_pe)
__device__ float d_scores[(long)H_ * S_ * S_];         // 16 x 2048 x 2048
__device__ float d_o1    [(long)H_ * S_ * LORA_];      // 16 x 2048 x 512
__device__ float d_o2    [(long)S_ * (H_ * VD_)];      // 2048 x 2048

// ---------------------------------------------------------------------------
// Generic batched SGEMM: C[z] = alpha * A[z] (MxK) * op(B[z])
//   BT=true : B is (N,K) row-major  -> C += A[m,k] * B[n,k]
//   BT=false: B is (K,N) row-major  -> C += A[m,k] * B[k,n]
// causal: 0 = none
//         1 = skip output tiles entirely above diagonal (col0 > row0+BM-1)
//         2 = limit K-loop to row0+BM (attn weights are 0 beyond diagonal)
// All M,N,K here are multiples of the tile sizes, so no bounds checks.
// ---------------------------------------------------------------------------
#define BM 64
#define BN 64
#define BK 16
#define TM 4
#define TN 4

template <bool BT>
__global__ void gemm_kernel(const float* __restrict__ A,
                            const float* __restrict__ B,
                            float* __restrict__ C,
                            int M, int N, int K,
                            int lda, int ldb, int ldc,
                            long sA, long sB, long sC,
                            float alpha, int causal)
{
    const int z = blockIdx.z;
    A += (long)z * sA;
    B += (long)z * sB;
    C += (long)z * sC;

    const int row0 = blockIdx.y * BM;
    const int col0 = blockIdx.x * BN;
    if (causal == 1 && col0 > row0 + BM - 1) return;
    int Klim = K;
    if (causal == 2) Klim = min(K, row0 + BM);

    __shared__ float As[BK][BM + 4];
    __shared__ float Bs[BK][BN + 4];

    const int tx = threadIdx.x;   // 0..15
    const int ty = threadIdx.y;   // 0..15
    const int tid = ty * 16 + tx;

    float acc[TM][TN];
#pragma unroll
    for (int i = 0; i < TM; i++)
#pragma unroll
        for (int j = 0; j < TN; j++) acc[i][j] = 0.f;

    for (int k0 = 0; k0 < Klim; k0 += BK) {
        // load A tile (coalesced along K)
#pragma unroll
        for (int i = tid; i < BM * BK; i += 256) {
            int m = i >> 4, kk = i & 15;
            As[kk][m] = A[(long)(row0 + m) * lda + (k0 + kk)];
        }
        // load B tile
        if (BT) {
#pragma unroll
            for (int i = tid; i < BN * BK; i += 256) {
                int n = i >> 4, kk = i & 15;
                Bs[kk][n] = B[(long)(col0 + n) * ldb + (k0 + kk)];
            }
        } else {
#pragma unroll
            for (int i = tid; i < BN * BK; i += 256) {
                int kk = i >> 6, n = i & 63;
                Bs[kk][n] = B[(long)(k0 + kk) * ldb + (col0 + n)];
            }
        }
        __syncthreads();

#pragma unroll
        for (int kk = 0; kk < BK; kk++) {
            float a[TM], b[TN];
#pragma unroll
            for (int i = 0; i < TM; i++) a[i] = As[kk][ty * TM + i];
#pragma unroll
            for (int j = 0; j < TN; j++) b[j] = Bs[kk][tx * TN + j];
#pragma unroll
            for (int i = 0; i < TM; i++)
#pragma unroll
                for (int j = 0; j < TN; j++)
                    acc[i][j] += a[i] * b[j];
        }
        __syncthreads();
    }

#pragma unroll
    for (int i = 0; i < TM; i++) {
        int gm = row0 + ty * TM + i;
#pragma unroll
        for (int j = 0; j < TN; j++) {
            int gn = col0 + tx * TN + j;
            C[(long)gm * ldc + gn] = acc[i][j] * alpha;
        }
    }
}

// ---------------------------------------------------------------------------
// Prep: rmsnorm(kv_c) + rope(k_pe) -> keff;  rope(q_pe) -> qeff[..., 512:576]
// one block per sequence position s
// ---------------------------------------------------------------------------
__global__ void prep_kernel(const float* __restrict__ q,
                            const float* __restrict__ kv,
                            const float* __restrict__ cosb,
                            const float* __restrict__ sinb,
                            const float* __restrict__ knw,
                            float* __restrict__ keff,
                            float* __restrict__ qeff)
{
    const int s = blockIdx.x;
    const int tid = threadIdx.x;     // 256 threads
    const float* kvrow = kv + (long)s * KVW_;
    __shared__ float red[256];

    // rmsnorm of kv_c (512)
    float ss = 0.f;
    for (int c = tid; c < LORA_; c += 256) {
        float v = kvrow[c];
        ss += v * v;
    }
    red[tid] = ss;
    __syncthreads();
    for (int w = 128; w > 0; w >>= 1) {
        if (tid < w) red[tid] += red[tid + w];
        __syncthreads();
    }
    float r = rsqrtf(red[0] / (float)LORA_ + 1e-6f);
    for (int c = tid; c < LORA_; c += 256)
        keff[(long)s * KVW_ + c] = kvrow[c] * r * knw[c];

    const float* cs = cosb + s * (ROPE_ / 2);
    const float* sn = sinb + s * (ROPE_ / 2);

    // rope k_pe (32 pairs)
    if (tid < 32) {
        int i = tid;
        float x0 = kvrow[LORA_ + 2 * i];
        float x1 = kvrow[LORA_ + 2 * i + 1];
        keff[(long)s * KVW_ + LORA_ + 2 * i]     = x0 * cs[i] - x1 * sn[i];
        keff[(long)s * KVW_ + LORA_ + 2 * i + 1] = x0 * sn[i] + x1 * cs[i];
    }

    // rope q_pe: 16 heads x 32 pairs
    for (int idx = tid; idx < H_ * 32; idx += 256) {
        int h = idx >> 5, i = idx & 31;
        const float* qrow = q + (long)s * (H_ * QKH_) + h * QKH_ + NOPE_;
        float x0 = qrow[2 * i];
        float x1 = qrow[2 * i + 1];
        float* dst = qeff + ((long)h * S_ + s) * KVW_ + LORA_;
        dst[2 * i]     = x0 * cs[i] - x1 * sn[i];
        dst[2 * i + 1] = x0 * sn[i] + x1 * cs[i];
    }
}

// ---------------------------------------------------------------------------
// Causal softmax in place over scores[h][s][0..s]; zeros beyond the diagonal.
// grid (S, H), block 256
// ---------------------------------------------------------------------------
__global__ void softmax_kernel(float* __restrict__ scores)
{
    const int s = blockIdx.x;
    const int h = blockIdx.y;
    float* row = scores + ((long)h * S_ + s) * S_;
    const int n = s + 1;
    const int tid = threadIdx.x;
    __shared__ float red[256];

    float m = -1e30f;
    for (int t = tid; t < n; t += 256) m = fmaxf(m, row[t]);
    red[tid] = m;
    __syncthreads();
    for (int w = 128; w > 0; w >>= 1) {
        if (tid < w) red[tid] = fmaxf(red[tid], red[tid + w]);
        __syncthreads();
    }
    m = red[0];
    __syncthreads();

    float sum = 0.f;
    for (int t = tid; t < n; t += 256) sum += __expf(row[t] - m);
    red[tid] = sum;
    __syncthreads();
    for (int w = 128; w > 0; w >>= 1) {
        if (tid < w) red[tid] += red[tid + w];
        __syncthreads();
    }
    float inv = 1.0f / red[0];

    for (int t = tid; t < n; t += 256) row[t] = __expf(row[t] - m) * inv;
    for (int t = n + tid; t < S_; t += 256) row[t] = 0.f;
}

// ---------------------------------------------------------------------------
// Launch
// ---------------------------------------------------------------------------
extern "C" void kernel_launch(void* const* d_in, const int* in_sizes, int n_in,
                              void* d_out, int out_size)
{
    const float* x     = (const float*)d_in[0];
    const float* cosb  = (const float*)d_in[1];
    const float* sinb  = (const float*)d_in[2];
    const float* wq    = (const float*)d_in[3];
    const float* wkv_a = (const float*)d_in[4];
    const float* knw   = (const float*)d_in[5];
    const float* wkv_b = (const float*)d_in[6];
    const float* wo    = (const float*)d_in[7];
    float* out = (float*)d_out;

    float *q, *kv, *qeff, *keff, *scores, *o1, *o2;
    cudaGetSymbolAddress((void**)&q,      d_q);
    cudaGetSymbolAddress((void**)&kv,     d_kv);
    cudaGetSymbolAddress((void**)&qeff,   d_qeff);
    cudaGetSymbolAddress((void**)&keff,   d_keff);
    cudaGetSymbolAddress((void**)&scores, d_scores);
    cudaGetSymbolAddress((void**)&o1,     d_o1);
    cudaGetSymbolAddress((void**)&o2,     d_o2);

    dim3 blk(16, 16);

    // 1. q = x @ wq^T   (2048 x 3072)
    gemm_kernel<true><<<dim3((H_ * QKH_) / BN, S_ / BM, 1), blk>>>(
        x, wq, q, S_, H_ * QKH_, DIM_, DIM_, DIM_, H_ * QKH_,
        0, 0, 0, 1.f, 0);

    // 2. kv = x @ wkv_a^T  (2048 x 576)
    gemm_kernel<true><<<dim3(KVW_ / BN, S_ / BM, 1), blk>>>(
        x, wkv_a, kv, S_, KVW_, DIM_, DIM_, DIM_, KVW_,
        0, 0, 0, 1.f, 0);

    // 3. rmsnorm + rope -> keff, qeff[...,512:576]
    prep_kernel<<<S_, 256>>>(q, kv, cosb, sinb, knw, keff, qeff);

    // 4. q_c[h] = q_nope[h] @ w_uk[h]  (per head 2048x512x128), into qeff[...,0:512]
    gemm_kernel<false><<<dim3(LORA_ / BN, S_ / BM, H_), blk>>>(
        q, wkv_b, qeff, S_, LORA_, NOPE_, H_ * QKH_, LORA_, KVW_,
        (long)QKH_, (long)(NOPE_ + VD_) * LORA_, (long)S_ * KVW_, 1.f, 0);

    // 5. scores[h] = SCALE * qeff[h] @ keff^T  (causal tile skip)
    gemm_kernel<true><<<dim3(S_ / BN, S_ / BM, H_), blk>>>(
        qeff, keff, scores, S_, S_, KVW_, KVW_, KVW_, S_,
        (long)S_ * KVW_, 0, (long)S_ * S_, SCALE_, 1);

    // 6. causal softmax in place
    softmax_kernel<<<dim3(S_, H_), 256>>>(scores);

    // 7. o1[h] = attn[h] @ kv_c_norm  (K limited by diagonal)
    gemm_kernel<false><<<dim3(LORA_ / BN, S_ / BM, H_), blk>>>(
        scores, keff, o1, S_, LORA_, S_, S_, KVW_, LORA_,
        (long)S_ * S_, 0, (long)S_ * LORA_, 1.f, 2);

    // 8. o2[:, h*128:(h+1)*128] = o1[h] @ w_uv[h]^T
    gemm_kernel<true><<<dim3(VD_ / BN, S_ / BM, H_), blk>>>(
        o1, wkv_b + (long)NOPE_ * LORA_, o2, S_, VD_, LORA_, LORA_, LORA_, H_ * VD_,
        (long)S_ * LORA_, (long)(NOPE_ + VD_) * LORA_, (long)VD_, 1.f, 0);

    // 9. out = o2 @ wo^T  (2048 x 2048)
    gemm_kernel<true><<<dim3(DIM_ / BN, S_ / BM, 1), blk>>>(
        o2, wo, out, S_, DIM_, H_ * VD_, H_ * VD_, H_ * VD_, DIM_,
        0, 0, 0, 1.f, 0);
}

// round 5
// speedup vs baseline: 3.2593x; 3.2593x over previous
#include <cuda_runtime.h>
#include <cuda_bf16.h>
#include <cstdint>

// ---------------------------------------------------------------------------
// Problem constants
// ---------------------------------------------------------------------------
#define S_ 2048
#define DIM_ 2048
#define H_ 16
#define NOPE_ 128
#define ROPE_ 64
#define VD_ 128
#define LORA_ 512
#define QKH_ 192            // NOPE + ROPE
#define KVW_ 576            // LORA + ROPE
#define KVP_ 640            // padded to multiple of 128
#define SCALE_ 0.07216878364870323f  // 192^-0.5

// ---------------------------------------------------------------------------
// Scratch
// ---------------------------------------------------------------------------
__device__ float d_q     [(long)S_ * 3072];          // q fp32 (for rope reads)
__device__ float d_kvpad [(long)S_ * KVP_];          // kv fp32 (padded)
__device__ float d_scores[(long)H_ * S_ * S_];       // pre-softmax scores fp32

__device__ __nv_bfloat16 d_xhi[(long)S_ * DIM_],      d_xlo[(long)S_ * DIM_];
__device__ __nv_bfloat16 d_wqhi[(long)3072 * DIM_],   d_wqlo[(long)3072 * DIM_];
__device__ __nv_bfloat16 d_wkvaphi[(long)KVP_ * DIM_],d_wkvaplo[(long)KVP_ * DIM_];
__device__ __nv_bfloat16 d_wohi[(long)DIM_ * DIM_],   d_wolo[(long)DIM_ * DIM_];
__device__ __nv_bfloat16 d_wkvbhi[(long)H_ * 256 * LORA_], d_wkvblo[(long)H_ * 256 * LORA_];
__device__ __nv_bfloat16 d_wukThi[(long)H_ * LORA_ * NOPE_], d_wukTlo[(long)H_ * LORA_ * NOPE_];
__device__ __nv_bfloat16 d_qhi[(long)S_ * 3072],      d_qlo[(long)S_ * 3072];
__device__ __nv_bfloat16 d_qeffhi[(long)H_ * S_ * KVW_], d_qefflo[(long)H_ * S_ * KVW_];
__device__ __nv_bfloat16 d_keffhi[(long)S_ * KVW_],   d_kefflo[(long)S_ * KVW_];
__device__ __nv_bfloat16 d_keffThi[(long)LORA_ * S_], d_keffTlo[(long)LORA_ * S_];
__device__ __nv_bfloat16 d_attnhi[(long)H_ * S_ * S_],d_attnlo[(long)H_ * S_ * S_];
__device__ __nv_bfloat16 d_o1hi[(long)H_ * S_ * LORA_], d_o1lo[(long)H_ * S_ * LORA_];
__device__ __nv_bfloat16 d_o2hi[(long)S_ * DIM_],     d_o2lo[(long)S_ * DIM_];

// ---------------------------------------------------------------------------
// Helpers
// ---------------------------------------------------------------------------
__device__ __forceinline__ uint32_t smem_u32(const void* p) {
    uint32_t a;
    asm("{ .reg .u64 t; cvta.to.shared.u64 t, %1; cvt.u32.u64 %0, t; }"
        : "=r"(a) : "l"(p));
    return a;
}

__device__ __forceinline__ void ldsm_x4(uint32_t* r, uint32_t addr) {
    asm volatile("ldmatrix.sync.aligned.m8n8.x4.shared.b16 {%0,%1,%2,%3}, [%4];"
                 : "=r"(r[0]), "=r"(r[1]), "=r"(r[2]), "=r"(r[3]) : "r"(addr));
}
__device__ __forceinline__ void ldsm_x2(uint32_t* r, uint32_t addr) {
    asm volatile("ldmatrix.sync.aligned.m8n8.x2.shared.b16 {%0,%1}, [%2];"
                 : "=r"(r[0]), "=r"(r[1]) : "r"(addr));
}
__device__ __forceinline__ void mma16816(float* c, const uint32_t* a, const uint32_t* b) {
    asm volatile(
        "mma.sync.aligned.m16n8k16.row.col.f32.bf16.bf16.f32 "
        "{%0,%1,%2,%3}, {%4,%5,%6,%7}, {%8,%9}, {%0,%1,%2,%3};"
        : "+f"(c[0]), "+f"(c[1]), "+f"(c[2]), "+f"(c[3])
        : "r"(a[0]), "r"(a[1]), "r"(a[2]), "r"(a[3]), "r"(b[0]), "r"(b[1]));
}

__device__ __forceinline__ void split2(float v, __nv_bfloat16& h, __nv_bfloat16& l) {
    h = __float2bfloat16(v);
    l = __float2bfloat16(v - __bfloat162float(h));
}

// ---------------------------------------------------------------------------
// bf16 split-precision GEMM via mma.sync:
//   C(z) = alpha * A(z)(M,K) @ B(z)(N,K)^T,  A/B given as hi/lo bf16 pairs,
//   C ~= Ahi.Bhi + Ahi.Blo + Alo.Bhi  (fp32 accum)
// CTA tile 128x128, K chunk 32, cp.async double buffer.
// SMEM tile layout: 128 rows x 80B pitch (64B data) -> conflict-free ldmatrix.
// grid = (N/128, M/128, Z); 256 threads (8 warps as 2(M) x 4(N), warp 64x32).
// causal: 1 = skip tiles with bx > by; 2 = Klim = min(K, row0+128)
// ---------------------------------------------------------------------------
#define TILE_B 10240            // 128 * 80
#define STAGE_B 40960           // 4 tiles
#define DSMEM_BYTES 81920       // 2 stages

__device__ __forceinline__ void load_tile32(uint32_t dst,
                                            const __nv_bfloat16* __restrict__ src,
                                            int rbase, int ld, int k0, int tid)
{
#pragma unroll
    for (int t = 0; t < 2; t++) {
        int o = tid + t * 256;          // 0..511 : 128 rows x 4 x 16B
        int row = o >> 2, c = o & 3;
        const void* g = (const void*)(src + (long)(rbase + row) * ld + k0 + c * 8);
        asm volatile("cp.async.cg.shared.global [%0], [%1], 16;"
                     :: "r"(dst + row * 80 + c * 16), "l"(g));
    }
}

__global__ void __launch_bounds__(256, 1)
tgemm(const __nv_bfloat16* __restrict__ Ahi, const __nv_bfloat16* __restrict__ Alo,
      long sA, int lda,
      const __nv_bfloat16* __restrict__ Bhi, const __nv_bfloat16* __restrict__ Blo,
      long sB, int ldb,
      float* Cf, __nv_bfloat16* Chi, __nv_bfloat16* Clo,
      long sC, int ldc,
      int K, float alpha, int causal)
{
    const int bx = blockIdx.x, by = blockIdx.y, z = blockIdx.z;
    if (causal == 1 && bx > by) return;
    const int row0 = by * 128, col0 = bx * 128;
    int Klim = (causal == 2) ? min(K, row0 + 128) : K;
    const int nc = Klim >> 5;

    Ahi += (long)z * sA;  Alo += (long)z * sA;
    Bhi += (long)z * sB;  Blo += (long)z * sB;
    if (Cf)  Cf  += (long)z * sC;
    if (Chi) { Chi += (long)z * sC; Clo += (long)z * sC; }

    extern __shared__ char dsm[];
    const uint32_t s0 = smem_u32(dsm);

    const int tid = threadIdx.x;
    const int lane = tid & 31;
    const int wid = tid >> 5;
    const int wm = wid & 1;          // 0..1  (M)
    const int wn = wid >> 1;         // 0..3  (N)

    float acc[4][4][4];
#pragma unroll
    for (int mt = 0; mt < 4; mt++)
#pragma unroll
        for (int nt = 0; nt < 4; nt++)
#pragma unroll
            for (int e = 0; e < 4; e++) acc[mt][nt][e] = 0.f;

    // prologue: fill stage 0
    {
        uint32_t sb = s0;
        load_tile32(sb,              Ahi, row0, lda, 0, tid);
        load_tile32(sb + TILE_B,     Alo, row0, lda, 0, tid);
        load_tile32(sb + 2 * TILE_B, Bhi, col0, ldb, 0, tid);
        load_tile32(sb + 3 * TILE_B, Blo, col0, ldb, 0, tid);
        asm volatile("cp.async.commit_group;" ::: "memory");
    }

    // fragment smem addressing (within a tile)
    const uint32_t a_off = (wm * 64 + (lane & 15)) * 80 + ((lane >> 4) << 4);
    const uint32_t b_off = (wn * 32 + (lane & 7)) * 80 + (((lane >> 3) & 1) << 4);

    for (int i = 0; i < nc; i++) {
        if (i + 1 < nc) {
            uint32_t sb = s0 + ((i + 1) & 1) * STAGE_B;
            int k0 = (i + 1) << 5;
            load_tile32(sb,              Ahi, row0, lda, k0, tid);
            load_tile32(sb + TILE_B,     Alo, row0, lda, k0, tid);
            load_tile32(sb + 2 * TILE_B, Bhi, col0, ldb, k0, tid);
            load_tile32(sb + 3 * TILE_B, Blo, col0, ldb, k0, tid);
            asm volatile("cp.async.commit_group;" ::: "memory");
            asm volatile("cp.async.wait_group 1;" ::: "memory");
        } else {
            asm volatile("cp.async.wait_group 0;" ::: "memory");
        }
        __syncthreads();

        const uint32_t sb = s0 + (i & 1) * STAGE_B;
#pragma unroll
        for (int ks = 0; ks < 2; ks++) {
            const uint32_t kb = ks * 32;
            uint32_t ah[4][4], al[4][4], bh[4][2], bl[4][2];
#pragma unroll
            for (int mt = 0; mt < 4; mt++) {
                ldsm_x4(ah[mt], sb + a_off + mt * (16 * 80) + kb);
                ldsm_x4(al[mt], sb + TILE_B + a_off + mt * (16 * 80) + kb);
            }
#pragma unroll
            for (int nt = 0; nt < 4; nt++) {
                ldsm_x2(bh[nt], sb + 2 * TILE_B + b_off + nt * (8 * 80) + kb);
                ldsm_x2(bl[nt], sb + 3 * TILE_B + b_off + nt * (8 * 80) + kb);
            }
#pragma unroll
            for (int mt = 0; mt < 4; mt++)
#pragma unroll
                for (int nt = 0; nt < 4; nt++) {
                    mma16816(acc[mt][nt], ah[mt], bh[nt]);
                    mma16816(acc[mt][nt], ah[mt], bl[nt]);
                    mma16816(acc[mt][nt], al[mt], bh[nt]);
                }
        }
        __syncthreads();
    }

    // ---------------- epilogue: stage through smem ----------------
    float* stage = (float*)dsm;   // pitch 132 f32: 128*132*4 = 67584 <= 81920
#pragma unroll
    for (int mt = 0; mt < 4; mt++) {
        int r = wm * 64 + mt * 16 + (lane >> 2);
#pragma unroll
        for (int nt = 0; nt < 4; nt++) {
            int c = wn * 32 + nt * 8 + (lane & 3) * 2;
            stage[r * 132 + c]           = acc[mt][nt][0] * alpha;
            stage[r * 132 + c + 1]       = acc[mt][nt][1] * alpha;
            stage[(r + 8) * 132 + c]     = acc[mt][nt][2] * alpha;
            stage[(r + 8) * 132 + c + 1] = acc[mt][nt][3] * alpha;
        }
    }
    __syncthreads();

#pragma unroll
    for (int it = 0; it < 16; it++) {
        int g = tid + it * 256;
        int m = g >> 5, cg = (g & 31) * 4;
        float v0 = stage[m * 132 + cg + 0];
        float v1 = stage[m * 132 + cg + 1];
        float v2 = stage[m * 132 + cg + 2];
        float v3 = stage[m * 132 + cg + 3];
        long off = (long)(row0 + m) * ldc + col0 + cg;
        if (Cf) {
            float4 v = make_float4(v0, v1, v2, v3);
            *(float4*)(Cf + off) = v;
        }
        if (Chi) {
            __nv_bfloat16 h0, h1, h2, h3, l0, l1, l2, l3;
            split2(v0, h0, l0); split2(v1, h1, l1);
            split2(v2, h2, l2); split2(v3, h3, l3);
            *(__nv_bfloat162*)(Chi + off)     = __nv_bfloat162(h0, h1);
            *(__nv_bfloat162*)(Chi + off + 2) = __nv_bfloat162(h2, h3);
            *(__nv_bfloat162*)(Clo + off)     = __nv_bfloat162(l0, l1);
            *(__nv_bfloat162*)(Clo + off + 2) = __nv_bfloat162(l2, l3);
        }
    }
}

// ---------------------------------------------------------------------------
// Pointwise / prep kernels
// ---------------------------------------------------------------------------
__global__ void split_kernel(const float* __restrict__ in,
                             __nv_bfloat16* __restrict__ hi,
                             __nv_bfloat16* __restrict__ lo, long n)
{
    long i = (long)blockIdx.x * blockDim.x + threadIdx.x;
    if (i < n) {
        __nv_bfloat16 h, l;
        split2(in[i], h, l);
        hi[i] = h; lo[i] = l;
    }
}

// pad wkv_a (576 x 2048) -> (640 x 2048) with zero rows, split
__global__ void padsplit_wkva(const float* __restrict__ in,
                              __nv_bfloat16* __restrict__ hi,
                              __nv_bfloat16* __restrict__ lo)
{
    long i = (long)blockIdx.x * blockDim.x + threadIdx.x;
    long n = (long)KVP_ * DIM_;
    if (i < n) {
        long r = i / DIM_, c = i % DIM_;
        float v = (r < KVW_) ? in[r * DIM_ + c] : 0.f;
        __nv_bfloat16 h, l;
        split2(v, h, l);
        hi[i] = h; lo[i] = l;
    }
}

// w_ukT[h][c][d] = wkv_b[(h*256+d)*512 + c], split. grid(16,4,16), block(32,32)
__global__ void wukt_kernel(const float* __restrict__ wkvb,
                            __nv_bfloat16* __restrict__ hi,
                            __nv_bfloat16* __restrict__ lo)
{
    __shared__ float tile[32][33];
    const int h = blockIdx.z;
    const int c0 = blockIdx.x * 32, d0 = blockIdx.y * 32;
    const int tx = threadIdx.x, ty = threadIdx.y;
    tile[ty][tx] = wkvb[((long)h * 256 + d0 + ty) * LORA_ + c0 + tx];
    __syncthreads();
    float v = tile[tx][ty];  // [d][c] -> out[c][d]
    __nv_bfloat16 hh, ll;
    split2(v, hh, ll);
    long o = (long)h * LORA_ * NOPE_ + (long)(c0 + ty) * NOPE_ + d0 + tx;
    hi[o] = hh; lo[o] = ll;
}

// transpose keff cols 0..511: out[c][t] = in[t][c]. grid(64,16), block(32,32)
__global__ void transT_bf16(const __nv_bfloat16* __restrict__ in,
                            __nv_bfloat16* __restrict__ out)
{
    __shared__ __nv_bfloat16 tile[32][33];
    const int t0 = blockIdx.x * 32, c0 = blockIdx.y * 32;
    const int tx = threadIdx.x, ty = threadIdx.y;
    tile[ty][tx] = in[(long)(t0 + ty) * KVW_ + c0 + tx];
    __syncthreads();
    out[(long)(c0 + ty) * S_ + t0 + tx] = tile[tx][ty];
}

// rmsnorm(kv_c)+rope(k_pe) -> keff hi/lo ; rope(q_pe) -> qeff cols 512..575
__global__ void prep_kernel(const float* __restrict__ q,
                            const float* __restrict__ kvpad,
                            const float* __restrict__ cosb,
                            const float* __restrict__ sinb,
                            const float* __restrict__ knw,
                            __nv_bfloat16* __restrict__ keffhi,
                            __nv_bfloat16* __restrict__ kefflo,
                            __nv_bfloat16* __restrict__ qeffhi,
                            __nv_bfloat16* __restrict__ qefflo)
{
    const int s = blockIdx.x;
    const int tid = threadIdx.x;
    const float* kvrow = kvpad + (long)s * KVP_;
    __shared__ float red[256];

    float ss = 0.f;
    for (int c = tid; c < LORA_; c += 256) { float v = kvrow[c]; ss += v * v; }
    red[tid] = ss;
    __syncthreads();
    for (int w = 128; w > 0; w >>= 1) {
        if (tid < w) red[tid] += red[tid + w];
        __syncthreads();
    }
    float r = rsqrtf(red[0] / (float)LORA_ + 1e-6f);
    for (int c = tid; c < LORA_; c += 256) {
        __nv_bfloat16 h, l;
        split2(kvrow[c] * r * knw[c], h, l);
        keffhi[(long)s * KVW_ + c] = h;
        kefflo[(long)s * KVW_ + c] = l;
    }

    const float* cs = cosb + s * (ROPE_ / 2);
    const float* sn = sinb + s * (ROPE_ / 2);

    if (tid < 32) {
        int i = tid;
        float x0 = kvrow[LORA_ + 2 * i], x1 = kvrow[LORA_ + 2 * i + 1];
        __nv_bfloat16 h, l;
        split2(x0 * cs[i] - x1 * sn[i], h, l);
        keffhi[(long)s * KVW_ + LORA_ + 2 * i] = h;
        kefflo[(long)s * KVW_ + LORA_ + 2 * i] = l;
        split2(x0 * sn[i] + x1 * cs[i], h, l);
        keffhi[(long)s * KVW_ + LORA_ + 2 * i + 1] = h;
        kefflo[(long)s * KVW_ + LORA_ + 2 * i + 1] = l;
    }

    for (int idx = tid; idx < H_ * 32; idx += 256) {
        int h = idx >> 5, i = idx & 31;
        const float* qrow = q + (long)s * 3072 + h * QKH_ + NOPE_;
        float x0 = qrow[2 * i], x1 = qrow[2 * i + 1];
        long base = ((long)h * S_ + s) * KVW_ + LORA_;
        __nv_bfloat16 hh, ll;
        split2(x0 * cs[i] - x1 * sn[i], hh, ll);
        qeffhi[base + 2 * i] = hh; qefflo[base + 2 * i] = ll;
        split2(x0 * sn[i] + x1 * cs[i], hh, ll);
        qeffhi[base + 2 * i + 1] = hh; qefflo[base + 2 * i + 1] = ll;
    }
}

// causal softmax over scores[h][s][0..s] -> attn hi/lo (zeros beyond diag)
__global__ void softmax_kernel(const float* __restrict__ scores,
                               __nv_bfloat16* __restrict__ attnhi,
                               __nv_bfloat16* __restrict__ attnlo)
{
    const int s = blockIdx.x, h = blockIdx.y;
    const float* row = scores + ((long)h * S_ + s) * S_;
    __nv_bfloat16* ohi = attnhi + ((long)h * S_ + s) * S_;
    __nv_bfloat16* olo = attnlo + ((long)h * S_ + s) * S_;
    const int n = s + 1;
    const int tid = threadIdx.x;
    __shared__ float red[256];

    float vals[8];
    float m = -1e30f;
#pragma unroll
    for (int j = 0; j < 8; j++) {
        int t = tid + j * 256;
        vals[j] = (t < n) ? row[t] : -1e30f;
        m = fmaxf(m, vals[j]);
    }
    red[tid] = m;
    __syncthreads();
    for (int w = 128; w > 0; w >>= 1) {
        if (tid < w) red[tid] = fmaxf(red[tid], red[tid + w]);
        __syncthreads();
    }
    m = red[0];
    __syncthreads();

    float sum = 0.f;
#pragma unroll
    for (int j = 0; j < 8; j++) {
        int t = tid + j * 256;
        if (t < n) { vals[j] = __expf(vals[j] - m); sum += vals[j]; }
    }
    red[tid] = sum;
    __syncthreads();
    for (int w = 128; w > 0; w >>= 1) {
        if (tid < w) red[tid] += red[tid + w];
        __syncthreads();
    }
    float inv = 1.0f / red[0];

#pragma unroll
    for (int j = 0; j < 8; j++) {
        int t = tid + j * 256;
        if (t < S_) {
            float p = (t < n) ? vals[j] * inv : 0.f;
            __nv_bfloat16 hh, ll;
            split2(p, hh, ll);
            ohi[t] = hh; olo[t] = ll;
        }
    }
}

// ---------------------------------------------------------------------------
// Launch
// ---------------------------------------------------------------------------
extern "C" void kernel_launch(void* const* d_in, const int* in_sizes, int n_in,
                              void* d_out, int out_size)
{
    const float* x     = (const float*)d_in[0];
    const float* cosb  = (const float*)d_in[1];
    const float* sinb  = (const float*)d_in[2];
    const float* wq    = (const float*)d_in[3];
    const float* wkv_a = (const float*)d_in[4];
    const float* knw   = (const float*)d_in[5];
    const float* wkv_b = (const float*)d_in[6];
    const float* wo    = (const float*)d_in[7];
    float* out = (float*)d_out;

    cudaFuncSetAttribute(tgemm, cudaFuncAttributeMaxDynamicSharedMemorySize,
                         DSMEM_BYTES);

    float *q, *kvpad, *scores;
    cudaGetSymbolAddress((void**)&q,      d_q);
    cudaGetSymbolAddress((void**)&kvpad,  d_kvpad);
    cudaGetSymbolAddress((void**)&scores, d_scores);

    __nv_bfloat16 *xhi,*xlo,*wqhi,*wqlo,*wkvaphi,*wkvaplo,*wohi,*wolo;
    __nv_bfloat16 *wkvbhi,*wkvblo,*wukThi,*wukTlo,*qhi,*qlo;
    __nv_bfloat16 *qeffhi,*qefflo,*keffhi,*kefflo,*keffThi,*keffTlo;
    __nv_bfloat16 *attnhi,*attnlo,*o1hi,*o1lo,*o2hi,*o2lo;
    cudaGetSymbolAddress((void**)&xhi, d_xhi);       cudaGetSymbolAddress((void**)&xlo, d_xlo);
    cudaGetSymbolAddress((void**)&wqhi, d_wqhi);     cudaGetSymbolAddress((void**)&wqlo, d_wqlo);
    cudaGetSymbolAddress((void**)&wkvaphi, d_wkvaphi); cudaGetSymbolAddress((void**)&wkvaplo, d_wkvaplo);
    cudaGetSymbolAddress((void**)&wohi, d_wohi);     cudaGetSymbolAddress((void**)&wolo, d_wolo);
    cudaGetSymbolAddress((void**)&wkvbhi, d_wkvbhi); cudaGetSymbolAddress((void**)&wkvblo, d_wkvblo);
    cudaGetSymbolAddress((void**)&wukThi, d_wukThi); cudaGetSymbolAddress((void**)&wukTlo, d_wukTlo);
    cudaGetSymbolAddress((void**)&qhi, d_qhi);       cudaGetSymbolAddress((void**)&qlo, d_qlo);
    cudaGetSymbolAddress((void**)&qeffhi, d_qeffhi); cudaGetSymbolAddress((void**)&qefflo, d_qefflo);
    cudaGetSymbolAddress((void**)&keffhi, d_keffhi); cudaGetSymbolAddress((void**)&kefflo, d_kefflo);
    cudaGetSymbolAddress((void**)&keffThi, d_keffThi); cudaGetSymbolAddress((void**)&keffTlo, d_keffTlo);
    cudaGetSymbolAddress((void**)&attnhi, d_attnhi); cudaGetSymbolAddress((void**)&attnlo, d_attnlo);
    cudaGetSymbolAddress((void**)&o1hi, d_o1hi);     cudaGetSymbolAddress((void**)&o1lo, d_o1lo);
    cudaGetSymbolAddress((void**)&o2hi, d_o2hi);     cudaGetSymbolAddress((void**)&o2lo, d_o2lo);

    // -------- operand splits --------
    {
        long n;
        n = (long)S_ * DIM_;
        split_kernel<<<(n + 255) / 256, 256>>>(x, xhi, xlo, n);
        n = (long)3072 * DIM_;
        split_kernel<<<(n + 255) / 256, 256>>>(wq, wqhi, wqlo, n);
        n = (long)DIM_ * DIM_;
        split_kernel<<<(n + 255) / 256, 256>>>(wo, wohi, wolo, n);
        n = (long)H_ * 256 * LORA_;
        split_kernel<<<(n + 255) / 256, 256>>>(wkv_b, wkvbhi, wkvblo, n);
        n = (long)KVP_ * DIM_;
        padsplit_wkva<<<(n + 255) / 256, 256>>>(wkv_a, wkvaphi, wkvaplo);
        wukt_kernel<<<dim3(16, 4, 16), dim3(32, 32)>>>(wkv_b, wukThi, wukTlo);
    }

    // 1. q = x @ wq^T  (2048 x 3072), f32 + hi/lo
    tgemm<<<dim3(3072 / 128, 16, 1), 256, DSMEM_BYTES>>>(
        xhi, xlo, 0, DIM_, wqhi, wqlo, 0, DIM_,
        q, qhi, qlo, 0, 3072, DIM_, 1.f, 0);

    // 2. kvpad = x @ wkv_a_pad^T  (2048 x 640), f32 only
    tgemm<<<dim3(KVP_ / 128, 16, 1), 256, DSMEM_BYTES>>>(
        xhi, xlo, 0, DIM_, wkvaphi, wkvaplo, 0, DIM_,
        kvpad, nullptr, nullptr, 0, KVP_, DIM_, 1.f, 0);

    // 3. prep: rmsnorm + rope
    prep_kernel<<<S_, 256>>>(q, kvpad, cosb, sinb, knw,
                             keffhi, kefflo, qeffhi, qefflo);

    // 4. q_c[h] -> qeff cols 0..511 (hi/lo)
    tgemm<<<dim3(LORA_ / 128, 16, H_), 256, DSMEM_BYTES>>>(
        qhi, qlo, (long)QKH_, 3072, wukThi, wukTlo, (long)LORA_ * NOPE_, NOPE_,
        nullptr, qeffhi, qefflo, (long)S_ * KVW_, KVW_, NOPE_, 1.f, 0);

    // 5. keffT (cols 0..511 transposed)
    transT_bf16<<<dim3(64, 16), dim3(32, 32)>>>(keffhi, keffThi);
    transT_bf16<<<dim3(64, 16), dim3(32, 32)>>>(kefflo, keffTlo);

    // 6. scores[h] = SCALE * qeff[h] @ keff^T (causal tile skip)
    tgemm<<<dim3(16, 16, H_), 256, DSMEM_BYTES>>>(
        qeffhi, qefflo, (long)S_ * KVW_, KVW_, keffhi, kefflo, 0, KVW_,
        scores, nullptr, nullptr, (long)S_ * S_, S_, KVW_, SCALE_, 1);

    // 7. softmax -> attn hi/lo
    softmax_kernel<<<dim3(S_, H_), 256>>>(scores, attnhi, attnlo);

    // 8. o1[h] = attn[h] @ kv_c  (B = keffT, K limited to diagonal)
    tgemm<<<dim3(LORA_ / 128, 16, H_), 256, DSMEM_BYTES>>>(
        attnhi, attnlo, (long)S_ * S_, S_, keffThi, keffTlo, 0, S_,
        nullptr, o1hi, o1lo, (long)S_ * LORA_, LORA_, S_, 1.f, 2);

    // 9. o2[:, h*128:+128] = o1[h] @ w_uv[h]^T
    tgemm<<<dim3(1, 16, H_), 256, DSMEM_BYTES>>>(
        o1hi, o1lo, (long)S_ * LORA_, LORA_,
        wkvbhi + (long)NOPE_ * LORA_, wkvblo + (long)NOPE_ * LORA_,
        (long)256 * LORA_, LORA_,
        nullptr, o2hi, o2lo, (long)VD_, DIM_, LORA_, 1.f, 0);

    // 10. out = o2 @ wo^T
    tgemm<<<dim3(16, 16, 1), 256, DSMEM_BYTES>>>(
        o2hi, o2lo, 0, DIM_, wohi, wolo, 0, DIM_,
        out, nullptr, nullptr, 0, DIM_, DIM_, 1.f, 0);
}

// round 6
// speedup vs baseline: 3.6466x; 1.1189x over previous
#include <cuda_runtime.h>
#include <cuda_bf16.h>
#include <cstdint>

// ---------------------------------------------------------------------------
// Problem constants
// ---------------------------------------------------------------------------
#define S_ 2048
#define DIM_ 2048
#define H_ 16
#define NOPE_ 128
#define ROPE_ 64
#define VD_ 128
#define LORA_ 512
#define QKH_ 192            // NOPE + ROPE
#define KVW_ 576            // LORA + ROPE
#define KVP_ 640            // padded to multiple of 128
#define SCALE_ 0.07216878364870323f  // 192^-0.5

// ---------------------------------------------------------------------------
// Scratch
// ---------------------------------------------------------------------------
__device__ float d_q     [(long)S_ * 3072];          // q fp32 (for rope reads)
__device__ float d_kvpad [(long)S_ * KVP_];          // kv fp32 (padded)
__device__ float d_scores[(long)H_ * S_ * S_];       // pre-softmax scores fp32

__device__ __nv_bfloat16 d_xhi[(long)S_ * DIM_],      d_xlo[(long)S_ * DIM_];
__device__ __nv_bfloat16 d_wqhi[(long)3072 * DIM_],   d_wqlo[(long)3072 * DIM_];
__device__ __nv_bfloat16 d_wkvaphi[(long)KVP_ * DIM_],d_wkvaplo[(long)KVP_ * DIM_];
__device__ __nv_bfloat16 d_wohi[(long)DIM_ * DIM_],   d_wolo[(long)DIM_ * DIM_];
__device__ __nv_bfloat16 d_wkvbhi[(long)H_ * 256 * LORA_], d_wkvblo[(long)H_ * 256 * LORA_];
__device__ __nv_bfloat16 d_wukThi[(long)H_ * LORA_ * NOPE_], d_wukTlo[(long)H_ * LORA_ * NOPE_];
__device__ __nv_bfloat16 d_qhi[(long)S_ * 3072],      d_qlo[(long)S_ * 3072];
__device__ __nv_bfloat16 d_qeffhi[(long)H_ * S_ * KVW_], d_qefflo[(long)H_ * S_ * KVW_];
__device__ __nv_bfloat16 d_keffhi[(long)S_ * KVW_],   d_kefflo[(long)S_ * KVW_];
__device__ __nv_bfloat16 d_keffThi[(long)LORA_ * S_], d_keffTlo[(long)LORA_ * S_];
__device__ __nv_bfloat16 d_attnhi[(long)H_ * S_ * S_],d_attnlo[(long)H_ * S_ * S_];
__device__ __nv_bfloat16 d_o1hi[(long)H_ * S_ * LORA_], d_o1lo[(long)H_ * S_ * LORA_];
__device__ __nv_bfloat16 d_o2hi[(long)S_ * DIM_],     d_o2lo[(long)S_ * DIM_];

// ---------------------------------------------------------------------------
// Helpers
// ---------------------------------------------------------------------------
__device__ __forceinline__ uint32_t smem_u32(const void* p) {
    uint32_t a;
    asm("{ .reg .u64 t; cvta.to.shared.u64 t, %1; cvt.u32.u64 %0, t; }"
        : "=r"(a) : "l"(p));
    return a;
}

__device__ __forceinline__ void ldsm_x4(uint32_t* r, uint32_t addr) {
    asm volatile("ldmatrix.sync.aligned.m8n8.x4.shared.b16 {%0,%1,%2,%3}, [%4];"
                 : "=r"(r[0]), "=r"(r[1]), "=r"(r[2]), "=r"(r[3]) : "r"(addr));
}
__device__ __forceinline__ void ldsm_x2(uint32_t* r, uint32_t addr) {
    asm volatile("ldmatrix.sync.aligned.m8n8.x2.shared.b16 {%0,%1}, [%2];"
                 : "=r"(r[0]), "=r"(r[1]) : "r"(addr));
}
__device__ __forceinline__ void mma16816(float* c, const uint32_t* a, const uint32_t* b) {
    asm volatile(
        "mma.sync.aligned.m16n8k16.row.col.f32.bf16.bf16.f32 "
        "{%0,%1,%2,%3}, {%4,%5,%6,%7}, {%8,%9}, {%0,%1,%2,%3};"
        : "+f"(c[0]), "+f"(c[1]), "+f"(c[2]), "+f"(c[3])
        : "r"(a[0]), "r"(a[1]), "r"(a[2]), "r"(a[3]), "r"(b[0]), "r"(b[1]));
}

__device__ __forceinline__ void split2(float v, __nv_bfloat16& h, __nv_bfloat16& l) {
    h = __float2bfloat16(v);
    l = __float2bfloat16(v - __bfloat162float(h));
}

// ---------------------------------------------------------------------------
// bf16 split-precision GEMM via mma.sync:
//   C(z) = alpha * A(z)(M,K) @ B(z)(N,K)^T,  A/B given as hi/lo bf16 pairs,
//   C ~= Ahi.Bhi + Ahi.Blo + Alo.Bhi  (fp32 accum)
// CTA tile 128x128, K chunk 32, cp.async double buffer, 2 CTAs/SM.
// SMEM tile layout: 128 rows x 80B pitch (64B data) -> conflict-free ldmatrix.
// grid = (N/128, M/128, Z); 256 threads (8 warps as 2(M) x 4(N), warp 64x32).
// causal: 1 = skip tiles with bx > by; 2 = Klim = min(K, row0+128)
// ---------------------------------------------------------------------------
#define TILE_B 10240            // 128 * 80
#define STAGE_B 40960           // 4 tiles
#define DSMEM_BYTES 81920       // 2 stages

__device__ __forceinline__ void load_tile32(uint32_t dst,
                                            const __nv_bfloat16* __restrict__ src,
                                            int rbase, int ld, int k0, int tid)
{
#pragma unroll
    for (int t = 0; t < 2; t++) {
        int o = tid + t * 256;          // 0..511 : 128 rows x 4 x 16B
        int row = o >> 2, c = o & 3;
        const void* g = (const void*)(src + (long)(rbase + row) * ld + k0 + c * 8);
        asm volatile("cp.async.cg.shared.global [%0], [%1], 16;"
                     :: "r"(dst + row * 80 + c * 16), "l"(g));
    }
}

__global__ void __launch_bounds__(256, 2)
tgemm(const __nv_bfloat16* __restrict__ Ahi, const __nv_bfloat16* __restrict__ Alo,
      long sA, int lda,
      const __nv_bfloat16* __restrict__ Bhi, const __nv_bfloat16* __restrict__ Blo,
      long sB, int ldb,
      float* Cf, __nv_bfloat16* Chi, __nv_bfloat16* Clo,
      long sC, int ldc,
      int K, float alpha, int causal)
{
    const int bx = blockIdx.x, by = blockIdx.y, z = blockIdx.z;
    if (causal == 1 && bx > by) return;
    const int row0 = by * 128, col0 = bx * 128;
    int Klim = (causal == 2) ? min(K, row0 + 128) : K;
    const int nc = Klim >> 5;

    Ahi += (long)z * sA;  Alo += (long)z * sA;
    Bhi += (long)z * sB;  Blo += (long)z * sB;
    if (Cf)  Cf  += (long)z * sC;
    if (Chi) { Chi += (long)z * sC; Clo += (long)z * sC; }

    extern __shared__ char dsm[];
    const uint32_t s0 = smem_u32(dsm);

    const int tid = threadIdx.x;
    const int lane = tid & 31;
    const int wid = tid >> 5;
    const int wm = wid & 1;          // 0..1  (M)
    const int wn = wid >> 1;         // 0..3  (N)

    float acc[4][4][4];
#pragma unroll
    for (int mt = 0; mt < 4; mt++)
#pragma unroll
        for (int nt = 0; nt < 4; nt++)
#pragma unroll
            for (int e = 0; e < 4; e++) acc[mt][nt][e] = 0.f;

    // prologue: fill stage 0
    {
        uint32_t sb = s0;
        load_tile32(sb,              Ahi, row0, lda, 0, tid);
        load_tile32(sb + TILE_B,     Alo, row0, lda, 0, tid);
        load_tile32(sb + 2 * TILE_B, Bhi, col0, ldb, 0, tid);
        load_tile32(sb + 3 * TILE_B, Blo, col0, ldb, 0, tid);
        asm volatile("cp.async.commit_group;" ::: "memory");
    }

    // fragment smem addressing (within a tile)
    const uint32_t a_off = (wm * 64 + (lane & 15)) * 80 + ((lane >> 4) << 4);
    const uint32_t b_off = (wn * 32 + (lane & 7)) * 80 + (((lane >> 3) & 1) << 4);

    for (int i = 0; i < nc; i++) {
        if (i + 1 < nc) {
            uint32_t sb = s0 + ((i + 1) & 1) * STAGE_B;
            int k0 = (i + 1) << 5;
            load_tile32(sb,              Ahi, row0, lda, k0, tid);
            load_tile32(sb + TILE_B,     Alo, row0, lda, k0, tid);
            load_tile32(sb + 2 * TILE_B, Bhi, col0, ldb, k0, tid);
            load_tile32(sb + 3 * TILE_B, Blo, col0, ldb, k0, tid);
            asm volatile("cp.async.commit_group;" ::: "memory");
            asm volatile("cp.async.wait_group 1;" ::: "memory");
        } else {
            asm volatile("cp.async.wait_group 0;" ::: "memory");
        }
        __syncthreads();

        const uint32_t sb = s0 + (i & 1) * STAGE_B;
#pragma unroll
        for (int ks = 0; ks < 2; ks++) {
            const uint32_t kb = ks * 32;
            uint32_t ah[4][4], al[4][4], bh[4][2], bl[4][2];
#pragma unroll
            for (int mt = 0; mt < 4; mt++) {
                ldsm_x4(ah[mt], sb + a_off + mt * (16 * 80) + kb);
                ldsm_x4(al[mt], sb + TILE_B + a_off + mt * (16 * 80) + kb);
            }
#pragma unroll
            for (int nt = 0; nt < 4; nt++) {
                ldsm_x2(bh[nt], sb + 2 * TILE_B + b_off + nt * (8 * 80) + kb);
                ldsm_x2(bl[nt], sb + 3 * TILE_B + b_off + nt * (8 * 80) + kb);
            }
#pragma unroll
            for (int mt = 0; mt < 4; mt++)
#pragma unroll
                for (int nt = 0; nt < 4; nt++) {
                    mma16816(acc[mt][nt], ah[mt], bh[nt]);
                    mma16816(acc[mt][nt], ah[mt], bl[nt]);
                    mma16816(acc[mt][nt], al[mt], bh[nt]);
                }
        }
        __syncthreads();
    }

    // ---------------- epilogue: stage through smem ----------------
    float* stage = (float*)dsm;   // pitch 132 f32: 128*132*4 = 67584 <= 81920
#pragma unroll
    for (int mt = 0; mt < 4; mt++) {
        int r = wm * 64 + mt * 16 + (lane >> 2);
#pragma unroll
        for (int nt = 0; nt < 4; nt++) {
            int c = wn * 32 + nt * 8 + (lane & 3) * 2;
            stage[r * 132 + c]           = acc[mt][nt][0] * alpha;
            stage[r * 132 + c + 1]       = acc[mt][nt][1] * alpha;
            stage[(r + 8) * 132 + c]     = acc[mt][nt][2] * alpha;
            stage[(r + 8) * 132 + c + 1] = acc[mt][nt][3] * alpha;
        }
    }
    __syncthreads();

#pragma unroll
    for (int it = 0; it < 16; it++) {
        int g = tid + it * 256;
        int m = g >> 5, cg = (g & 31) * 4;
        float v0 = stage[m * 132 + cg + 0];
        float v1 = stage[m * 132 + cg + 1];
        float v2 = stage[m * 132 + cg + 2];
        float v3 = stage[m * 132 + cg + 3];
        long off = (long)(row0 + m) * ldc + col0 + cg;
        if (Cf) {
            float4 v = make_float4(v0, v1, v2, v3);
            *(float4*)(Cf + off) = v;
        }
        if (Chi) {
            __nv_bfloat16 h0, h1, h2, h3, l0, l1, l2, l3;
            split2(v0, h0, l0); split2(v1, h1, l1);
            split2(v2, h2, l2); split2(v3, h3, l3);
            *(__nv_bfloat162*)(Chi + off)     = __nv_bfloat162(h0, h1);
            *(__nv_bfloat162*)(Chi + off + 2) = __nv_bfloat162(h2, h3);
            *(__nv_bfloat162*)(Clo + off)     = __nv_bfloat162(l0, l1);
            *(__nv_bfloat162*)(Clo + off + 2) = __nv_bfloat162(l2, l3);
        }
    }
}

// ---------------------------------------------------------------------------
// Pointwise / prep kernels
// ---------------------------------------------------------------------------
// vectorized: 4 floats / thread
__global__ void split_kernel(const float4* __restrict__ in,
                             __nv_bfloat162* __restrict__ hi,
                             __nv_bfloat162* __restrict__ lo, long n4)
{
    long i = (long)blockIdx.x * blockDim.x + threadIdx.x;
    if (i < n4) {
        float4 v = in[i];
        __nv_bfloat16 h0, h1, h2, h3, l0, l1, l2, l3;
        split2(v.x, h0, l0); split2(v.y, h1, l1);
        split2(v.z, h2, l2); split2(v.w, h3, l3);
        hi[2 * i]     = __nv_bfloat162(h0, h1);
        hi[2 * i + 1] = __nv_bfloat162(h2, h3);
        lo[2 * i]     = __nv_bfloat162(l0, l1);
        lo[2 * i + 1] = __nv_bfloat162(l2, l3);
    }
}

// pad wkv_a (576 x 2048) -> (640 x 2048) with zero rows, split (4 wide)
__global__ void padsplit_wkva(const float4* __restrict__ in,
                              __nv_bfloat162* __restrict__ hi,
                              __nv_bfloat162* __restrict__ lo)
{
    long i = (long)blockIdx.x * blockDim.x + threadIdx.x;  // float4 index
    long n4 = (long)KVP_ * DIM_ / 4;
    if (i < n4) {
        long r = i / (DIM_ / 4);
        float4 v = (r < KVW_) ? in[i] : make_float4(0.f, 0.f, 0.f, 0.f);
        __nv_bfloat16 h0, h1, h2, h3, l0, l1, l2, l3;
        split2(v.x, h0, l0); split2(v.y, h1, l1);
        split2(v.z, h2, l2); split2(v.w, h3, l3);
        hi[2 * i]     = __nv_bfloat162(h0, h1);
        hi[2 * i + 1] = __nv_bfloat162(h2, h3);
        lo[2 * i]     = __nv_bfloat162(l0, l1);
        lo[2 * i + 1] = __nv_bfloat162(l2, l3);
    }
}

// w_ukT[h][c][d] = wkv_b[(h*256+d)*512 + c], split. grid(16,4,16), block(32,32)
__global__ void wukt_kernel(const float* __restrict__ wkvb,
                            __nv_bfloat16* __restrict__ hi,
                            __nv_bfloat16* __restrict__ lo)
{
    __shared__ float tile[32][33];
    const int h = blockIdx.z;
    const int c0 = blockIdx.x * 32, d0 = blockIdx.y * 32;
    const int tx = threadIdx.x, ty = threadIdx.y;
    tile[ty][tx] = wkvb[((long)h * 256 + d0 + ty) * LORA_ + c0 + tx];
    __syncthreads();
    float v = tile[tx][ty];  // [d][c] -> out[c][d]
    __nv_bfloat16 hh, ll;
    split2(v, hh, ll);
    long o = (long)h * LORA_ * NOPE_ + (long)(c0 + ty) * NOPE_ + d0 + tx;
    hi[o] = hh; lo[o] = ll;
}

// transpose keff cols 0..511: out[c][t] = in[t][c]. grid(64,16), block(32,32)
__global__ void transT_bf16(const __nv_bfloat16* __restrict__ in,
                            __nv_bfloat16* __restrict__ out)
{
    __shared__ __nv_bfloat16 tile[32][33];
    const int t0 = blockIdx.x * 32, c0 = blockIdx.y * 32;
    const int tx = threadIdx.x, ty = threadIdx.y;
    tile[ty][tx] = in[(long)(t0 + ty) * KVW_ + c0 + tx];
    __syncthreads();
    out[(long)(c0 + ty) * S_ + t0 + tx] = tile[tx][ty];
}

// rmsnorm(kv_c)+rope(k_pe) -> keff hi/lo ; rope(q_pe) -> qeff cols 512..575
__global__ void prep_kernel(const float* __restrict__ q,
                            const float* __restrict__ kvpad,
                            const float* __restrict__ cosb,
                            const float* __restrict__ sinb,
                            const float* __restrict__ knw,
                            __nv_bfloat16* __restrict__ keffhi,
                            __nv_bfloat16* __restrict__ kefflo,
                            __nv_bfloat16* __restrict__ qeffhi,
                            __nv_bfloat16* __restrict__ qefflo)
{
    const int s = blockIdx.x;
    const int tid = threadIdx.x;
    const float* kvrow = kvpad + (long)s * KVP_;
    __shared__ float red[256];

    float ss = 0.f;
    for (int c = tid; c < LORA_; c += 256) { float v = kvrow[c]; ss += v * v; }
    red[tid] = ss;
    __syncthreads();
    for (int w = 128; w > 0; w >>= 1) {
        if (tid < w) red[tid] += red[tid + w];
        __syncthreads();
    }
    float r = rsqrtf(red[0] / (float)LORA_ + 1e-6f);
    for (int c = tid; c < LORA_; c += 256) {
        __nv_bfloat16 h, l;
        split2(kvrow[c] * r * knw[c], h, l);
        keffhi[(long)s * KVW_ + c] = h;
        kefflo[(long)s * KVW_ + c] = l;
    }

    const float* cs = cosb + s * (ROPE_ / 2);
    const float* sn = sinb + s * (ROPE_ / 2);

    if (tid < 32) {
        int i = tid;
        float x0 = kvrow[LORA_ + 2 * i], x1 = kvrow[LORA_ + 2 * i + 1];
        __nv_bfloat16 h, l;
        split2(x0 * cs[i] - x1 * sn[i], h, l);
        keffhi[(long)s * KVW_ + LORA_ + 2 * i] = h;
        kefflo[(long)s * KVW_ + LORA_ + 2 * i] = l;
        split2(x0 * sn[i] + x1 * cs[i], h, l);
        keffhi[(long)s * KVW_ + LORA_ + 2 * i + 1] = h;
        kefflo[(long)s * KVW_ + LORA_ + 2 * i + 1] = l;
    }

    for (int idx = tid; idx < H_ * 32; idx += 256) {
        int h = idx >> 5, i = idx & 31;
        const float* qrow = q + (long)s * 3072 + h * QKH_ + NOPE_;
        float x0 = qrow[2 * i], x1 = qrow[2 * i + 1];
        long base = ((long)h * S_ + s) * KVW_ + LORA_;
        __nv_bfloat16 hh, ll;
        split2(x0 * cs[i] - x1 * sn[i], hh, ll);
        qeffhi[base + 2 * i] = hh; qefflo[base + 2 * i] = ll;
        split2(x0 * sn[i] + x1 * cs[i], hh, ll);
        qeffhi[base + 2 * i + 1] = hh; qefflo[base + 2 * i + 1] = ll;
    }
}

// causal softmax over scores[h][s][0..s] -> attn hi/lo.
// Zero-fill only up to the 128-aligned diagonal tile boundary (o1 never reads
// past Klim = row-tile end).
__global__ void softmax_kernel(const float* __restrict__ scores,
                               __nv_bfloat16* __restrict__ attnhi,
                               __nv_bfloat16* __restrict__ attnlo)
{
    const int s = blockIdx.x, h = blockIdx.y;
    const float* row = scores + ((long)h * S_ + s) * S_;
    __nv_bfloat16* ohi = attnhi + ((long)h * S_ + s) * S_;
    __nv_bfloat16* olo = attnlo + ((long)h * S_ + s) * S_;
    const int n = s + 1;
    const int nz = ((s >> 7) + 1) << 7;   // round up to 128
    const int tid = threadIdx.x;
    __shared__ float red[256];

    float vals[8];
    float m = -1e30f;
#pragma unroll
    for (int j = 0; j < 8; j++) {
        int t = tid + j * 256;
        vals[j] = (t < n) ? row[t] : -1e30f;
        m = fmaxf(m, vals[j]);
    }
    red[tid] = m;
    __syncthreads();
    for (int w = 128; w > 0; w >>= 1) {
        if (tid < w) red[tid] = fmaxf(red[tid], red[tid + w]);
        __syncthreads();
    }
    m = red[0];
    __syncthreads();

    float sum = 0.f;
#pragma unroll
    for (int j = 0; j < 8; j++) {
        int t = tid + j * 256;
        if (t < n) { vals[j] = __expf(vals[j] - m); sum += vals[j]; }
    }
    red[tid] = sum;
    __syncthreads();
    for (int w = 128; w > 0; w >>= 1) {
        if (tid < w) red[tid] += red[tid + w];
        __syncthreads();
    }
    float inv = 1.0f / red[0];

#pragma unroll
    for (int j = 0; j < 8; j++) {
        int t = tid + j * 256;
        if (t < nz) {
            float p = (t < n) ? vals[j] * inv : 0.f;
            __nv_bfloat16 hh, ll;
            split2(p, hh, ll);
            ohi[t] = hh; olo[t] = ll;
        }
    }
}

// ---------------------------------------------------------------------------
// Launch
// ---------------------------------------------------------------------------
extern "C" void kernel_launch(void* const* d_in, const int* in_sizes, int n_in,
                              void* d_out, int out_size)
{
    const float* x     = (const float*)d_in[0];
    const float* cosb  = (const float*)d_in[1];
    const float* sinb  = (const float*)d_in[2];
    const float* wq    = (const float*)d_in[3];
    const float* wkv_a = (const float*)d_in[4];
    const float* knw   = (const float*)d_in[5];
    const float* wkv_b = (const float*)d_in[6];
    const float* wo    = (const float*)d_in[7];
    float* out = (float*)d_out;

    cudaFuncSetAttribute(tgemm, cudaFuncAttributeMaxDynamicSharedMemorySize,
                         DSMEM_BYTES);

    float *q, *kvpad, *scores;
    cudaGetSymbolAddress((void**)&q,      d_q);
    cudaGetSymbolAddress((void**)&kvpad,  d_kvpad);
    cudaGetSymbolAddress((void**)&scores, d_scores);

    __nv_bfloat16 *xhi,*xlo,*wqhi,*wqlo,*wkvaphi,*wkvaplo,*wohi,*wolo;
    __nv_bfloat16 *wkvbhi,*wkvblo,*wukThi,*wukTlo,*qhi,*qlo;
    __nv_bfloat16 *qeffhi,*qefflo,*keffhi,*kefflo,*keffThi,*keffTlo;
    __nv_bfloat16 *attnhi,*attnlo,*o1hi,*o1lo,*o2hi,*o2lo;
    cudaGetSymbolAddress((void**)&xhi, d_xhi);       cudaGetSymbolAddress((void**)&xlo, d_xlo);
    cudaGetSymbolAddress((void**)&wqhi, d_wqhi);     cudaGetSymbolAddress((void**)&wqlo, d_wqlo);
    cudaGetSymbolAddress((void**)&wkvaphi, d_wkvaphi); cudaGetSymbolAddress((void**)&wkvaplo, d_wkvaplo);
    cudaGetSymbolAddress((void**)&wohi, d_wohi);     cudaGetSymbolAddress((void**)&wolo, d_wolo);
    cudaGetSymbolAddress((void**)&wkvbhi, d_wkvbhi); cudaGetSymbolAddress((void**)&wkvblo, d_wkvblo);
    cudaGetSymbolAddress((void**)&wukThi, d_wukThi); cudaGetSymbolAddress((void**)&wukTlo, d_wukTlo);
    cudaGetSymbolAddress((void**)&qhi, d_qhi);       cudaGetSymbolAddress((void**)&qlo, d_qlo);
    cudaGetSymbolAddress((void**)&qeffhi, d_qeffhi); cudaGetSymbolAddress((void**)&qefflo, d_qefflo);
    cudaGetSymbolAddress((void**)&keffhi, d_keffhi); cudaGetSymbolAddress((void**)&kefflo, d_kefflo);
    cudaGetSymbolAddress((void**)&keffThi, d_keffThi); cudaGetSymbolAddress((void**)&keffTlo, d_keffTlo);
    cudaGetSymbolAddress((void**)&attnhi, d_attnhi); cudaGetSymbolAddress((void**)&attnlo, d_attnlo);
    cudaGetSymbolAddress((void**)&o1hi, d_o1hi);     cudaGetSymbolAddress((void**)&o1lo, d_o1lo);
    cudaGetSymbolAddress((void**)&o2hi, d_o2hi);     cudaGetSymbolAddress((void**)&o2lo, d_o2lo);

    // -------- operand splits (float4-vectorized) --------
    {
        long n4;
        n4 = (long)S_ * DIM_ / 4;
        split_kernel<<<(n4 + 255) / 256, 256>>>(
            (const float4*)x, (__nv_bfloat162*)xhi, (__nv_bfloat162*)xlo, n4);
        n4 = (long)3072 * DIM_ / 4;
        split_kernel<<<(n4 + 255) / 256, 256>>>(
            (const float4*)wq, (__nv_bfloat162*)wqhi, (__nv_bfloat162*)wqlo, n4);
        n4 = (long)DIM_ * DIM_ / 4;
        split_kernel<<<(n4 + 255) / 256, 256>>>(
            (const float4*)wo, (__nv_bfloat162*)wohi, (__nv_bfloat162*)wolo, n4);
        n4 = (long)H_ * 256 * LORA_ / 4;
        split_kernel<<<(n4 + 255) / 256, 256>>>(
            (const float4*)wkv_b, (__nv_bfloat162*)wkvbhi, (__nv_bfloat162*)wkvblo, n4);
        n4 = (long)KVP_ * DIM_ / 4;
        padsplit_wkva<<<(n4 + 255) / 256, 256>>>(
            (const float4*)wkv_a, (__nv_bfloat162*)wkvaphi, (__nv_bfloat162*)wkvaplo);
        wukt_kernel<<<dim3(16, 4, 16), dim3(32, 32)>>>(wkv_b, wukThi, wukTlo);
    }

    // 1. q = x @ wq^T  (2048 x 3072), f32 + hi/lo
    tgemm<<<dim3(3072 / 128, 16, 1), 256, DSMEM_BYTES>>>(
        xhi, xlo, 0, DIM_, wqhi, wqlo, 0, DIM_,
        q, qhi, qlo, 0, 3072, DIM_, 1.f, 0);

    // 2. kvpad = x @ wkv_a_pad^T  (2048 x 640), f32 only
    tgemm<<<dim3(KVP_ / 128, 16, 1), 256, DSMEM_BYTES>>>(
        xhi, xlo, 0, DIM_, wkvaphi, wkvaplo, 0, DIM_,
        kvpad, nullptr, nullptr, 0, KVP_, DIM_, 1.f, 0);

    // 3. prep: rmsnorm + rope
    prep_kernel<<<S_, 256>>>(q, kvpad, cosb, sinb, knw,
                             keffhi, kefflo, qeffhi, qefflo);

    // 4. q_c[h] -> qeff cols 0..511 (hi/lo)
    tgemm<<<dim3(LORA_ / 128, 16, H_), 256, DSMEM_BYTES>>>(
        qhi, qlo, (long)QKH_, 3072, wukThi, wukTlo, (long)LORA_ * NOPE_, NOPE_,
        nullptr, qeffhi, qefflo, (long)S_ * KVW_, KVW_, NOPE_, 1.f, 0);

    // 5. keffT (cols 0..511 transposed)
    transT_bf16<<<dim3(64, 16), dim3(32, 32)>>>(keffhi, keffThi);
    transT_bf16<<<dim3(64, 16), dim3(32, 32)>>>(kefflo, keffTlo);

    // 6. scores[h] = SCALE * qeff[h] @ keff^T (causal tile skip)
    tgemm<<<dim3(16, 16, H_), 256, DSMEM_BYTES>>>(
        qeffhi, qefflo, (long)S_ * KVW_, KVW_, keffhi, kefflo, 0, KVW_,
        scores, nullptr, nullptr, (long)S_ * S_, S_, KVW_, SCALE_, 1);

    // 7. softmax -> attn hi/lo
    softmax_kernel<<<dim3(S_, H_), 256>>>(scores, attnhi, attnlo);

    // 8. o1[h] = attn[h] @ kv_c  (B = keffT, K limited to diagonal)
    tgemm<<<dim3(LORA_ / 128, 16, H_), 256, DSMEM_BYTES>>>(
        attnhi, attnlo, (long)S_ * S_, S_, keffThi, keffTlo, 0, S_,
        nullptr, o1hi, o1lo, (long)S_ * LORA_, LORA_, S_, 1.f, 2);

    // 9. o2[:, h*128:+128] = o1[h] @ w_uv[h]^T
    tgemm<<<dim3(1, 16, H_), 256, DSMEM_BYTES>>>(
        o1hi, o1lo, (long)S_ * LORA_, LORA_,
        wkvbhi + (long)NOPE_ * LORA_, wkvblo + (long)NOPE_ * LORA_,
        (long)256 * LORA_, LORA_,
        nullptr, o2hi, o2lo, (long)VD_, DIM_, LORA_, 1.f, 0);

    // 10. out = o2 @ wo^T
    tgemm<<<dim3(16, 16, 1), 256, DSMEM_BYTES>>>(
        o2hi, o2lo, 0, DIM_, wohi, wolo, 0, DIM_,
        out, nullptr, nullptr, 0, DIM_, DIM_, 1.f, 0);
}

// round 7
// speedup vs baseline: 3.8894x; 1.0666x over previous
#include <cuda_runtime.h>
#include <cuda_bf16.h>
#include <cstdint>

// ---------------------------------------------------------------------------
// Problem constants
// ---------------------------------------------------------------------------
#define S_ 2048
#define DIM_ 2048
#define H_ 16
#define NOPE_ 128
#define ROPE_ 64
#define VD_ 128
#define LORA_ 512
#define QKH_ 192            // NOPE + ROPE
#define KVW_ 576            // LORA + ROPE
#define NQKV_ 3712          // 3072 (q) + 640 (kv padded)
#define SCALE_ 0.07216878364870323f  // 192^-0.5

// ---------------------------------------------------------------------------
// Scratch
// ---------------------------------------------------------------------------
__device__ float d_qc    [(long)S_ * NQKV_];         // [q | kvpad] fp32
__device__ float d_scores[(long)H_ * S_ * S_];       // pre-softmax scores fp32

__device__ __nv_bfloat16 d_xhi[(long)S_ * DIM_],      d_xlo[(long)S_ * DIM_];
__device__ __nv_bfloat16 d_wqkvhi[(long)NQKV_ * DIM_],d_wqkvlo[(long)NQKV_ * DIM_];
__device__ __nv_bfloat16 d_wohi[(long)DIM_ * DIM_],   d_wolo[(long)DIM_ * DIM_];
__device__ __nv_bfloat16 d_wkvbhi[(long)H_ * 256 * LORA_], d_wkvblo[(long)H_ * 256 * LORA_];
__device__ __nv_bfloat16 d_wukThi[(long)H_ * LORA_ * NOPE_], d_wukTlo[(long)H_ * LORA_ * NOPE_];
__device__ __nv_bfloat16 d_qchi[(long)S_ * NQKV_],    d_qclo[(long)S_ * NQKV_];
__device__ __nv_bfloat16 d_qeffhi[(long)H_ * S_ * KVW_], d_qefflo[(long)H_ * S_ * KVW_];
__device__ __nv_bfloat16 d_keffhi[(long)S_ * KVW_],   d_kefflo[(long)S_ * KVW_];
__device__ __nv_bfloat16 d_keffThi[(long)LORA_ * S_], d_keffTlo[(long)LORA_ * S_];
__device__ __nv_bfloat16 d_attnhi[(long)H_ * S_ * S_],d_attnlo[(long)H_ * S_ * S_];
__device__ __nv_bfloat16 d_o1hi[(long)H_ * S_ * LORA_], d_o1lo[(long)H_ * S_ * LORA_];
__device__ __nv_bfloat16 d_o2hi[(long)S_ * DIM_],     d_o2lo[(long)S_ * DIM_];

// ---------------------------------------------------------------------------
// Helpers
// ---------------------------------------------------------------------------
__device__ __forceinline__ uint32_t smem_u32(const void* p) {
    uint32_t a;
    asm("{ .reg .u64 t; cvta.to.shared.u64 t, %1; cvt.u32.u64 %0, t; }"
        : "=r"(a) : "l"(p));
    return a;
}

__device__ __forceinline__ void ldsm_x4(uint32_t* r, uint32_t addr) {
    asm volatile("ldmatrix.sync.aligned.m8n8.x4.shared.b16 {%0,%1,%2,%3}, [%4];"
                 : "=r"(r[0]), "=r"(r[1]), "=r"(r[2]), "=r"(r[3]) : "r"(addr));
}
__device__ __forceinline__ void ldsm_x2(uint32_t* r, uint32_t addr) {
    asm volatile("ldmatrix.sync.aligned.m8n8.x2.shared.b16 {%0,%1}, [%2];"
                 : "=r"(r[0]), "=r"(r[1]) : "r"(addr));
}
__device__ __forceinline__ void mma16816(float* c, const uint32_t* a, const uint32_t* b) {
    asm volatile(
        "mma.sync.aligned.m16n8k16.row.col.f32.bf16.bf16.f32 "
        "{%0,%1,%2,%3}, {%4,%5,%6,%7}, {%8,%9}, {%0,%1,%2,%3};"
        : "+f"(c[0]), "+f"(c[1]), "+f"(c[2]), "+f"(c[3])
        : "r"(a[0]), "r"(a[1]), "r"(a[2]), "r"(a[3]), "r"(b[0]), "r"(b[1]));
}

__device__ __forceinline__ void split2(float v, __nv_bfloat16& h, __nv_bfloat16& l) {
    h = __float2bfloat16(v);
    l = __float2bfloat16(v - __bfloat162float(h));
}

// ---------------------------------------------------------------------------
// bf16 split-precision GEMM via mma.sync:
//   C(z) = alpha * A(z)(M,K) @ B(z)(N,K)^T
//   C ~= Ahi.Bhi + Ahi.Blo + Alo.Bhi  (fp32 accum)
// CTA tile 128x128, K chunk 32, cp.async double buffer, 2 CTAs/SM.
// SMEM: 128 rows x 80B pitch -> conflict-free ldmatrix.
// grid = (N/128, M/128, Z); 256 threads (8 warps, warp 64x32).
// causal: 1 = skip tiles with bx > by; 2 = Klim = min(K, row0+128)
// ---------------------------------------------------------------------------
#define TILE_B 10240            // 128 * 80
#define STAGE_B 40960           // 4 tiles
#define DSMEM_BYTES 81920       // 2 stages

__device__ __forceinline__ void load_tile32(uint32_t dst,
                                            const __nv_bfloat16* __restrict__ src,
                                            int rbase, int ld, int k0, int tid)
{
#pragma unroll
    for (int t = 0; t < 2; t++) {
        int o = tid + t * 256;          // 0..511 : 128 rows x 4 x 16B
        int row = o >> 2, c = o & 3;
        const void* g = (const void*)(src + (long)(rbase + row) * ld + k0 + c * 8);
        asm volatile("cp.async.cg.shared.global [%0], [%1], 16;"
                     :: "r"(dst + row * 80 + c * 16), "l"(g));
    }
}

__global__ void __launch_bounds__(256, 2)
tgemm(const __nv_bfloat16* __restrict__ Ahi, const __nv_bfloat16* __restrict__ Alo,
      long sA, int lda,
      const __nv_bfloat16* __restrict__ Bhi, const __nv_bfloat16* __restrict__ Blo,
      long sB, int ldb,
      float* Cf, __nv_bfloat16* Chi, __nv_bfloat16* Clo,
      long sC, int ldc,
      int K, float alpha, int causal)
{
    const int bx = blockIdx.x, by = blockIdx.y, z = blockIdx.z;
    if (causal == 1 && bx > by) return;
    const int row0 = by * 128, col0 = bx * 128;
    int Klim = (causal == 2) ? min(K, row0 + 128) : K;
    const int nc = Klim >> 5;

    Ahi += (long)z * sA;  Alo += (long)z * sA;
    Bhi += (long)z * sB;  Blo += (long)z * sB;
    if (Cf)  Cf  += (long)z * sC;
    if (Chi) { Chi += (long)z * sC; Clo += (long)z * sC; }

    extern __shared__ char dsm[];
    const uint32_t s0 = smem_u32(dsm);

    const int tid = threadIdx.x;
    const int lane = tid & 31;
    const int wid = tid >> 5;
    const int wm = wid & 1;          // 0..1  (M)
    const int wn = wid >> 1;         // 0..3  (N)

    float acc[4][4][4];
#pragma unroll
    for (int mt = 0; mt < 4; mt++)
#pragma unroll
        for (int nt = 0; nt < 4; nt++)
#pragma unroll
            for (int e = 0; e < 4; e++) acc[mt][nt][e] = 0.f;

    // prologue: fill stage 0
    {
        uint32_t sb = s0;
        load_tile32(sb,              Ahi, row0, lda, 0, tid);
        load_tile32(sb + TILE_B,     Alo, row0, lda, 0, tid);
        load_tile32(sb + 2 * TILE_B, Bhi, col0, ldb, 0, tid);
        load_tile32(sb + 3 * TILE_B, Blo, col0, ldb, 0, tid);
        asm volatile("cp.async.commit_group;" ::: "memory");
    }

    const uint32_t a_off = (wm * 64 + (lane & 15)) * 80 + ((lane >> 4) << 4);
    const uint32_t b_off = (wn * 32 + (lane & 7)) * 80 + (((lane >> 3) & 1) << 4);

    for (int i = 0; i < nc; i++) {
        if (i + 1 < nc) {
            uint32_t sb = s0 + ((i + 1) & 1) * STAGE_B;
            int k0 = (i + 1) << 5;
            load_tile32(sb,              Ahi, row0, lda, k0, tid);
            load_tile32(sb + TILE_B,     Alo, row0, lda, k0, tid);
            load_tile32(sb + 2 * TILE_B, Bhi, col0, ldb, k0, tid);
            load_tile32(sb + 3 * TILE_B, Blo, col0, ldb, k0, tid);
            asm volatile("cp.async.commit_group;" ::: "memory");
            asm volatile("cp.async.wait_group 1;" ::: "memory");
        } else {
            asm volatile("cp.async.wait_group 0;" ::: "memory");
        }
        __syncthreads();

        const uint32_t sb = s0 + (i & 1) * STAGE_B;
#pragma unroll
        for (int ks = 0; ks < 2; ks++) {
            const uint32_t kb = ks * 32;
            // preload B fragments only (16 regs live)
            uint32_t bh[4][2], bl[4][2];
#pragma unroll
            for (int nt = 0; nt < 4; nt++) {
                ldsm_x2(bh[nt], sb + 2 * TILE_B + b_off + nt * (8 * 80) + kb);
                ldsm_x2(bl[nt], sb + 3 * TILE_B + b_off + nt * (8 * 80) + kb);
            }
            // stream A fragments one mt at a time (8 regs live)
#pragma unroll
            for (int mt = 0; mt < 4; mt++) {
                uint32_t ah[4], al[4];
                ldsm_x4(ah, sb + a_off + mt * (16 * 80) + kb);
                ldsm_x4(al, sb + TILE_B + a_off + mt * (16 * 80) + kb);
#pragma unroll
                for (int nt = 0; nt < 4; nt++) {
                    mma16816(acc[mt][nt], ah, bh[nt]);
                    mma16816(acc[mt][nt], ah, bl[nt]);
                    mma16816(acc[mt][nt], al, bh[nt]);
                }
            }
        }
        __syncthreads();
    }

    // ---------------- epilogue: stage through smem ----------------
    float* stage = (float*)dsm;   // pitch 132 f32: 128*132*4 = 67584 <= 81920
#pragma unroll
    for (int mt = 0; mt < 4; mt++) {
        int r = wm * 64 + mt * 16 + (lane >> 2);
#pragma unroll
        for (int nt = 0; nt < 4; nt++) {
            int c = wn * 32 + nt * 8 + (lane & 3) * 2;
            stage[r * 132 + c]           = acc[mt][nt][0] * alpha;
            stage[r * 132 + c + 1]       = acc[mt][nt][1] * alpha;
            stage[(r + 8) * 132 + c]     = acc[mt][nt][2] * alpha;
            stage[(r + 8) * 132 + c + 1] = acc[mt][nt][3] * alpha;
        }
    }
    __syncthreads();

#pragma unroll
    for (int it = 0; it < 16; it++) {
        int g = tid + it * 256;
        int m = g >> 5, cg = (g & 31) * 4;
        float v0 = stage[m * 132 + cg + 0];
        float v1 = stage[m * 132 + cg + 1];
        float v2 = stage[m * 132 + cg + 2];
        float v3 = stage[m * 132 + cg + 3];
        long off = (long)(row0 + m) * ldc + col0 + cg;
        if (Cf) {
            float4 v = make_float4(v0, v1, v2, v3);
            *(float4*)(Cf + off) = v;
        }
        if (Chi) {
            __nv_bfloat16 h0, h1, h2, h3, l0, l1, l2, l3;
            split2(v0, h0, l0); split2(v1, h1, l1);
            split2(v2, h2, l2); split2(v3, h3, l3);
            *(__nv_bfloat162*)(Chi + off)     = __nv_bfloat162(h0, h1);
            *(__nv_bfloat162*)(Chi + off + 2) = __nv_bfloat162(h2, h3);
            *(__nv_bfloat162*)(Clo + off)     = __nv_bfloat162(l0, l1);
            *(__nv_bfloat162*)(Clo + off + 2) = __nv_bfloat162(l2, l3);
        }
    }
}

// ---------------------------------------------------------------------------
// Pointwise / prep kernels
// ---------------------------------------------------------------------------
__global__ void split_kernel(const float4* __restrict__ in,
                             __nv_bfloat162* __restrict__ hi,
                             __nv_bfloat162* __restrict__ lo, long n4)
{
    long i = (long)blockIdx.x * blockDim.x + threadIdx.x;
    if (i < n4) {
        float4 v = in[i];
        __nv_bfloat16 h0, h1, h2, h3, l0, l1, l2, l3;
        split2(v.x, h0, l0); split2(v.y, h1, l1);
        split2(v.z, h2, l2); split2(v.w, h3, l3);
        hi[2 * i]     = __nv_bfloat162(h0, h1);
        hi[2 * i + 1] = __nv_bfloat162(h2, h3);
        lo[2 * i]     = __nv_bfloat162(l0, l1);
        lo[2 * i + 1] = __nv_bfloat162(l2, l3);
    }
}

// concat wq (3072x2048) + wkv_a (576x2048, zero-padded to 640) -> 3712x2048
__global__ void split_concat_wqkv(const float4* __restrict__ wq,
                                  const float4* __restrict__ wkva,
                                  __nv_bfloat162* __restrict__ hi,
                                  __nv_bfloat162* __restrict__ lo)
{
    long i = (long)blockIdx.x * blockDim.x + threadIdx.x;  // float4 index
    long n4 = (long)NQKV_ * DIM_ / 4;
    if (i < n4) {
        long r = i / (DIM_ / 4);
        float4 v;
        if (r < 3072)            v = wq[i];
        else if (r < 3072 + KVW_) v = wkva[i - (long)3072 * (DIM_ / 4)];
        else                     v = make_float4(0.f, 0.f, 0.f, 0.f);
        __nv_bfloat16 h0, h1, h2, h3, l0, l1, l2, l3;
        split2(v.x, h0, l0); split2(v.y, h1, l1);
        split2(v.z, h2, l2); split2(v.w, h3, l3);
        hi[2 * i]     = __nv_bfloat162(h0, h1);
        hi[2 * i + 1] = __nv_bfloat162(h2, h3);
        lo[2 * i]     = __nv_bfloat162(l0, l1);
        lo[2 * i + 1] = __nv_bfloat162(l2, l3);
    }
}

// w_ukT[h][c][d] = wkv_b[(h*256+d)*512 + c], split. grid(16,4,16), block(32,32)
__global__ void wukt_kernel(const float* __restrict__ wkvb,
                            __nv_bfloat16* __restrict__ hi,
                            __nv_bfloat16* __restrict__ lo)
{
    __shared__ float tile[32][33];
    const int h = blockIdx.z;
    const int c0 = blockIdx.x * 32, d0 = blockIdx.y * 32;
    const int tx = threadIdx.x, ty = threadIdx.y;
    tile[ty][tx] = wkvb[((long)h * 256 + d0 + ty) * LORA_ + c0 + tx];
    __syncthreads();
    float v = tile[tx][ty];  // [d][c] -> out[c][d]
    __nv_bfloat16 hh, ll;
    split2(v, hh, ll);
    long o = (long)h * LORA_ * NOPE_ + (long)(c0 + ty) * NOPE_ + d0 + tx;
    hi[o] = hh; lo[o] = ll;
}

// transpose keff cols 0..511: out[c][t] = in[t][c]. grid(64,16), block(32,32)
__global__ void transT_bf16(const __nv_bfloat16* __restrict__ in,
                            __nv_bfloat16* __restrict__ out)
{
    __shared__ __nv_bfloat16 tile[32][33];
    const int t0 = blockIdx.x * 32, c0 = blockIdx.y * 32;
    const int tx = threadIdx.x, ty = threadIdx.y;
    tile[ty][tx] = in[(long)(t0 + ty) * KVW_ + c0 + tx];
    __syncthreads();
    out[(long)(c0 + ty) * S_ + t0 + tx] = tile[tx][ty];
}

// rmsnorm(kv_c)+rope(k_pe) -> keff hi/lo ; rope(q_pe) -> qeff cols 512..575
// q/kv both live in qc (ld NQKV_): q at col 0, kv at col 3072.
__global__ void prep_kernel(const float* __restrict__ qc,
                            const float* __restrict__ cosb,
                            const float* __restrict__ sinb,
                            const float* __restrict__ knw,
                            __nv_bfloat16* __restrict__ keffhi,
                            __nv_bfloat16* __restrict__ kefflo,
                            __nv_bfloat16* __restrict__ qeffhi,
                            __nv_bfloat16* __restrict__ qefflo)
{
    const int s = blockIdx.x;
    const int tid = threadIdx.x;
    const float* kvrow = qc + (long)s * NQKV_ + 3072;
    __shared__ float red[256];

    float ss = 0.f;
    for (int c = tid; c < LORA_; c += 256) { float v = kvrow[c]; ss += v * v; }
    red[tid] = ss;
    __syncthreads();
    for (int w = 128; w > 0; w >>= 1) {
        if (tid < w) red[tid] += red[tid + w];
        __syncthreads();
    }
    float r = rsqrtf(red[0] / (float)LORA_ + 1e-6f);
    for (int c = tid; c < LORA_; c += 256) {
        __nv_bfloat16 h, l;
        split2(kvrow[c] * r * knw[c], h, l);
        keffhi[(long)s * KVW_ + c] = h;
        kefflo[(long)s * KVW_ + c] = l;
    }

    const float* cs = cosb + s * (ROPE_ / 2);
    const float* sn = sinb + s * (ROPE_ / 2);

    if (tid < 32) {
        int i = tid;
        float x0 = kvrow[LORA_ + 2 * i], x1 = kvrow[LORA_ + 2 * i + 1];
        __nv_bfloat16 h, l;
        split2(x0 * cs[i] - x1 * sn[i], h, l);
        keffhi[(long)s * KVW_ + LORA_ + 2 * i] = h;
        kefflo[(long)s * KVW_ + LORA_ + 2 * i] = l;
        split2(x0 * sn[i] + x1 * cs[i], h, l);
        keffhi[(long)s * KVW_ + LORA_ + 2 * i + 1] = h;
        kefflo[(long)s * KVW_ + LORA_ + 2 * i + 1] = l;
    }

    for (int idx = tid; idx < H_ * 32; idx += 256) {
        int h = idx >> 5, i = idx & 31;
        const float* qrow = qc + (long)s * NQKV_ + h * QKH_ + NOPE_;
        float x0 = qrow[2 * i], x1 = qrow[2 * i + 1];
        long base = ((long)h * S_ + s) * KVW_ + LORA_;
        __nv_bfloat16 hh, ll;
        split2(x0 * cs[i] - x1 * sn[i], hh, ll);
        qeffhi[base + 2 * i] = hh; qefflo[base + 2 * i] = ll;
        split2(x0 * sn[i] + x1 * cs[i], hh, ll);
        qeffhi[base + 2 * i + 1] = hh; qefflo[base + 2 * i + 1] = ll;
    }
}

// causal softmax over scores[h][s][0..s] -> attn hi/lo.
// Thread t owns 8 contiguous cols; float4 reads, bf162 stores.
// Zero-fill only to the 128-aligned diagonal tile boundary.
__global__ void softmax_kernel(const float* __restrict__ scores,
                               __nv_bfloat16* __restrict__ attnhi,
                               __nv_bfloat16* __restrict__ attnlo)
{
    const int s = blockIdx.x, h = blockIdx.y;
    const float* row = scores + ((long)h * S_ + s) * S_;
    __nv_bfloat16* ohi = attnhi + ((long)h * S_ + s) * S_;
    __nv_bfloat16* olo = attnlo + ((long)h * S_ + s) * S_;
    const int n = s + 1;
    const int nz = ((s >> 7) + 1) << 7;   // round up to 128
    const int tid = threadIdx.x;
    const int lane = tid & 31, wid = tid >> 5;
    const int c0 = tid * 8;
    __shared__ float wred[8];

    float vals[8];
    float m = -1e30f;
    if (c0 < nz) {
        float4 v0 = *(const float4*)(row + c0);
        float4 v1 = *(const float4*)(row + c0 + 4);
        vals[0] = v0.x; vals[1] = v0.y; vals[2] = v0.z; vals[3] = v0.w;
        vals[4] = v1.x; vals[5] = v1.y; vals[6] = v1.z; vals[7] = v1.w;
#pragma unroll
        for (int j = 0; j < 8; j++)
            if (c0 + j < n) m = fmaxf(m, vals[j]);
    }
#pragma unroll
    for (int o = 16; o > 0; o >>= 1)
        m = fmaxf(m, __shfl_xor_sync(0xffffffffu, m, o));
    if (lane == 0) wred[wid] = m;
    __syncthreads();
    m = -1e30f;
#pragma unroll
    for (int w = 0; w < 8; w++) m = fmaxf(m, wred[w]);
    __syncthreads();

    float sum = 0.f;
    if (c0 < nz) {
#pragma unroll
        for (int j = 0; j < 8; j++) {
            float e = (c0 + j < n) ? __expf(vals[j] - m) : 0.f;
            vals[j] = e;
            sum += e;
        }
    }
#pragma unroll
    for (int o = 16; o > 0; o >>= 1)
        sum += __shfl_xor_sync(0xffffffffu, sum, o);
    if (lane == 0) wred[wid] = sum;
    __syncthreads();
    sum = 0.f;
#pragma unroll
    for (int w = 0; w < 8; w++) sum += wred[w];
    float inv = 1.0f / sum;

    if (c0 < nz) {
        __nv_bfloat162 hv[4], lv[4];
#pragma unroll
        for (int j = 0; j < 4; j++) {
            __nv_bfloat16 h0, h1, l0, l1;
            split2(vals[2 * j] * inv, h0, l0);
            split2(vals[2 * j + 1] * inv, h1, l1);
            hv[j] = __nv_bfloat162(h0, h1);
            lv[j] = __nv_bfloat162(l0, l1);
        }
        *(uint4*)(ohi + c0) = *(uint4*)hv;
        *(uint4*)(olo + c0) = *(uint4*)lv;
    }
}

// ---------------------------------------------------------------------------
// Launch
// ---------------------------------------------------------------------------
extern "C" void kernel_launch(void* const* d_in, const int* in_sizes, int n_in,
                              void* d_out, int out_size)
{
    const float* x     = (const float*)d_in[0];
    const float* cosb  = (const float*)d_in[1];
    const float* sinb  = (const float*)d_in[2];
    const float* wq    = (const float*)d_in[3];
    const float* wkv_a = (const float*)d_in[4];
    const float* knw   = (const float*)d_in[5];
    const float* wkv_b = (const float*)d_in[6];
    const float* wo    = (const float*)d_in[7];
    float* out = (float*)d_out;

    cudaFuncSetAttribute(tgemm, cudaFuncAttributeMaxDynamicSharedMemorySize,
                         DSMEM_BYTES);

    float *qc, *scores;
    cudaGetSymbolAddress((void**)&qc,     d_qc);
    cudaGetSymbolAddress((void**)&scores, d_scores);

    __nv_bfloat16 *xhi,*xlo,*wqkvhi,*wqkvlo,*wohi,*wolo;
    __nv_bfloat16 *wkvbhi,*wkvblo,*wukThi,*wukTlo,*qchi,*qclo;
    __nv_bfloat16 *qeffhi,*qefflo,*keffhi,*kefflo,*keffThi,*keffTlo;
    __nv_bfloat16 *attnhi,*attnlo,*o1hi,*o1lo,*o2hi,*o2lo;
    cudaGetSymbolAddress((void**)&xhi, d_xhi);       cudaGetSymbolAddress((void**)&xlo, d_xlo);
    cudaGetSymbolAddress((void**)&wqkvhi, d_wqkvhi); cudaGetSymbolAddress((void**)&wqkvlo, d_wqkvlo);
    cudaGetSymbolAddress((void**)&wohi, d_wohi);     cudaGetSymbolAddress((void**)&wolo, d_wolo);
    cudaGetSymbolAddress((void**)&wkvbhi, d_wkvbhi); cudaGetSymbolAddress((void**)&wkvblo, d_wkvblo);
    cudaGetSymbolAddress((void**)&wukThi, d_wukThi); cudaGetSymbolAddress((void**)&wukTlo, d_wukTlo);
    cudaGetSymbolAddress((void**)&qchi, d_qchi);     cudaGetSymbolAddress((void**)&qclo, d_qclo);
    cudaGetSymbolAddress((void**)&qeffhi, d_qeffhi); cudaGetSymbolAddress((void**)&qefflo, d_qefflo);
    cudaGetSymbolAddress((void**)&keffhi, d_keffhi); cudaGetSymbolAddress((void**)&kefflo, d_kefflo);
    cudaGetSymbolAddress((void**)&keffThi, d_keffThi); cudaGetSymbolAddress((void**)&keffTlo, d_keffTlo);
    cudaGetSymbolAddress((void**)&attnhi, d_attnhi); cudaGetSymbolAddress((void**)&attnlo, d_attnlo);
    cudaGetSymbolAddress((void**)&o1hi, d_o1hi);     cudaGetSymbolAddress((void**)&o1lo, d_o1lo);
    cudaGetSymbolAddress((void**)&o2hi, d_o2hi);     cudaGetSymbolAddress((void**)&o2lo, d_o2lo);

    // -------- operand splits --------
    {
        long n4;
        n4 = (long)S_ * DIM_ / 4;
        split_kernel<<<(n4 + 255) / 256, 256>>>(
            (const float4*)x, (__nv_bfloat162*)xhi, (__nv_bfloat162*)xlo, n4);
        n4 = (long)NQKV_ * DIM_ / 4;
        split_concat_wqkv<<<(n4 + 255) / 256, 256>>>(
            (const float4*)wq, (const float4*)wkv_a,
            (__nv_bfloat162*)wqkvhi, (__nv_bfloat162*)wqkvlo);
        n4 = (long)DIM_ * DIM_ / 4;
        split_kernel<<<(n4 + 255) / 256, 256>>>(
            (const float4*)wo, (__nv_bfloat162*)wohi, (__nv_bfloat162*)wolo, n4);
        n4 = (long)H_ * 256 * LORA_ / 4;
        split_kernel<<<(n4 + 255) / 256, 256>>>(
            (const float4*)wkv_b, (__nv_bfloat162*)wkvbhi, (__nv_bfloat162*)wkvblo, n4);
        wukt_kernel<<<dim3(16, 4, 16), dim3(32, 32)>>>(wkv_b, wukThi, wukTlo);
    }

    // 1. [q | kv] = x @ [wq | wkv_a]^T  (2048 x 3712), f32 + hi/lo
    tgemm<<<dim3(NQKV_ / 128, 16, 1), 256, DSMEM_BYTES>>>(
        xhi, xlo, 0, DIM_, wqkvhi, wqkvlo, 0, DIM_,
        qc, qchi, qclo, 0, NQKV_, DIM_, 1.f, 0);

    // 2. prep: rmsnorm + rope
    prep_kernel<<<S_, 256>>>(qc, cosb, sinb, knw,
                             keffhi, kefflo, qeffhi, qefflo);

    // 3. q_c[h] -> qeff cols 0..511 (hi/lo)
    tgemm<<<dim3(LORA_ / 128, 16, H_), 256, DSMEM_BYTES>>>(
        qchi, qclo, (long)QKH_, NQKV_, wukThi, wukTlo, (long)LORA_ * NOPE_, NOPE_,
        nullptr, qeffhi, qefflo, (long)S_ * KVW_, KVW_, NOPE_, 1.f, 0);

    // 4. keffT (cols 0..511 transposed)
    transT_bf16<<<dim3(64, 16), dim3(32, 32)>>>(keffhi, keffThi);
    transT_bf16<<<dim3(64, 16), dim3(32, 32)>>>(kefflo, keffTlo);

    // 5. scores[h] = SCALE * qeff[h] @ keff^T (causal tile skip)
    tgemm<<<dim3(16, 16, H_), 256, DSMEM_BYTES>>>(
        qeffhi, qefflo, (long)S_ * KVW_, KVW_, keffhi, kefflo, 0, KVW_,
        scores, nullptr, nullptr, (long)S_ * S_, S_, KVW_, SCALE_, 1);

    // 6. softmax -> attn hi/lo
    softmax_kernel<<<dim3(S_, H_), 256>>>(scores, attnhi, attnlo);

    // 7. o1[h] = attn[h] @ kv_c  (B = keffT, K limited to diagonal)
    tgemm<<<dim3(LORA_ / 128, 16, H_), 256, DSMEM_BYTES>>>(
        attnhi, attnlo, (long)S_ * S_, S_, keffThi, keffTlo, 0, S_,
        nullptr, o1hi, o1lo, (long)S_ * LORA_, LORA_, S_, 1.f, 2);

    // 8. o2[:, h*128:+128] = o1[h] @ w_uv[h]^T
    tgemm<<<dim3(1, 16, H_), 256, DSMEM_BYTES>>>(
        o1hi, o1lo, (long)S_ * LORA_, LORA_,
        wkvbhi + (long)NOPE_ * LORA_, wkvblo + (long)NOPE_ * LORA_,
        (long)256 * LORA_, LORA_,
        nullptr, o2hi, o2lo, (long)VD_, DIM_, LORA_, 1.f, 0);

    // 9. out = o2 @ wo^T
    tgemm<<<dim3(16, 16, 1), 256, DSMEM_BYTES>>>(
        o2hi, o2lo, 0, DIM_, wohi, wolo, 0, DIM_,
        out, nullptr, nullptr, 0, DIM_, DIM_, 1.f, 0);
}